// round 1
// baseline (speedup 1.0000x reference)
#include <cuda_runtime.h>
#include <math.h>

#define NN 20000
#define NE 320000
#define DD 128
#define DD3 384
#define LNUM 3

// ---------------- scratch (static device globals; no runtime allocation) ----------------
__device__ float g_filters[(size_t)NE * DD3];   // 491.5 MB, precomputed once per launch
__device__ float g_dir[(size_t)NE * 4];
__device__ float g_q[(size_t)NN * DD];
__device__ float g_h[(size_t)NN * DD];          // reused: inter hidden + mix hidden
__device__ float g_x[(size_t)NN * DD3];
__device__ float g_mu[(size_t)NN * DD3];        // (N,3,128)
__device__ float g_dmu[(size_t)NN * DD3];
__device__ float g_mumix[(size_t)NN * 768];     // (3N,256): [mu_V | mu_W]
__device__ float g_ctx[(size_t)NN * 256];
__device__ float g_dot[(size_t)NN * DD];
__device__ float g_xm[(size_t)NN * DD3];
__device__ float g_munode[(size_t)NN * DD3];

__device__ __forceinline__ float siluf(float x) { return x / (1.0f + expf(-x)); }
__device__ __forceinline__ float clip5(float x) { return fminf(fmaxf(x, -5.0f), 5.0f); }

// ---------------- generic fp32 GEMM: C = act(A[M,K] @ B[K,Nc] + bias) ----------------
// BM=BN=128, BK=8, 256 threads, 8x8 per thread. K % 8 == 0, Nc % 128 == 0 (holds here).
template<int ACT>
__global__ __launch_bounds__(256) void sgemm(const float* __restrict__ A,
                                             const float* __restrict__ B,
                                             const float* __restrict__ bias,
                                             float* __restrict__ C,
                                             int M, int K, int Nc)
{
    __shared__ float As[8][128];
    __shared__ float Bs[8][128];
    int tid = threadIdx.x;
    int tx = tid & 15, ty = tid >> 4;
    int row0 = blockIdx.y * 128, col0 = blockIdx.x * 128;
    int arow = tid >> 1, acol = (tid & 1) * 4;
    int brow = tid >> 5, bcol = (tid & 31) * 4;

    float acc[8][8];
#pragma unroll
    for (int i = 0; i < 8; i++)
#pragma unroll
        for (int j = 0; j < 8; j++) acc[i][j] = 0.0f;

    for (int k0 = 0; k0 < K; k0 += 8) {
        float4 av = make_float4(0.f, 0.f, 0.f, 0.f);
        int ar = row0 + arow;
        if (ar < M) av = *(const float4*)(A + (size_t)ar * K + k0 + acol);
        As[acol + 0][arow] = av.x; As[acol + 1][arow] = av.y;
        As[acol + 2][arow] = av.z; As[acol + 3][arow] = av.w;
        float4 bv = *(const float4*)(B + (size_t)(k0 + brow) * Nc + col0 + bcol);
        *(float4*)(&Bs[brow][bcol]) = bv;
        __syncthreads();
#pragma unroll
        for (int k = 0; k < 8; k++) {
            float a[8], b[8];
            *(float4*)(a)     = *(const float4*)(&As[k][ty * 8]);
            *(float4*)(a + 4) = *(const float4*)(&As[k][ty * 8 + 4]);
            *(float4*)(b)     = *(const float4*)(&Bs[k][tx * 8]);
            *(float4*)(b + 4) = *(const float4*)(&Bs[k][tx * 8 + 4]);
#pragma unroll
            for (int i = 0; i < 8; i++)
#pragma unroll
                for (int j = 0; j < 8; j++) acc[i][j] += a[i] * b[j];
        }
        __syncthreads();
    }

#pragma unroll
    for (int i = 0; i < 8; i++) {
        int r = row0 + ty * 8 + i;
        if (r >= M) continue;
#pragma unroll
        for (int jj = 0; jj < 2; jj++) {
            int cb = col0 + tx * 8 + jj * 4;
            float v0 = acc[i][jj * 4 + 0], v1 = acc[i][jj * 4 + 1];
            float v2 = acc[i][jj * 4 + 2], v3 = acc[i][jj * 4 + 3];
            if (bias) { v0 += bias[cb]; v1 += bias[cb + 1]; v2 += bias[cb + 2]; v3 += bias[cb + 3]; }
            if (ACT == 1) { v0 = siluf(v0); v1 = siluf(v1); v2 = siluf(v2); v3 = siluf(v3); }
            *(float4*)(C + (size_t)r * Nc + cb) = make_float4(v0, v1, v2, v3);
        }
    }
}

// ---------------- zero scratch accumulators ----------------
__global__ void zero_bufs()
{
    int idx = blockIdx.x * blockDim.x + threadIdx.x;
    if (idx < NN * DD3) { g_mu[idx] = 0.f; g_dmu[idx] = 0.f; g_munode[idx] = 0.f; }
}

// ---------------- per-edge geometry + RBF filters (truncated Gaussian window) ----------------
// warp per edge; lane owns 3 float4 column groups (12 of 384 outputs).
__global__ __launch_bounds__(256) void edge_pre(const float* __restrict__ pos,
                                                const int* __restrict__ ei,
                                                const float* __restrict__ fw,
                                                const float* __restrict__ fb)
{
    int e = blockIdx.x * 8 + (threadIdx.x >> 5);
    if (e >= NE) return;
    int lane = threadIdx.x & 31;
    int i = ei[e], j = ei[NE + e];
    float rx = pos[j * 3 + 0] - pos[i * 3 + 0];
    float ry = pos[j * 3 + 1] - pos[i * 3 + 1];
    float rz = pos[j * 3 + 2] - pos[i * 3 + 2];
    float d = sqrtf(rx * rx + ry * ry + rz * rz);
    d = fmaxf(d, 1e-8f);
    float dv = (lane == 0) ? rx : ((lane == 1) ? ry : rz);
    if (lane < 3) g_dir[(size_t)e * 4 + lane] = dv / d;

    const float spacing = 5.0f / 63.0f;
    const float coeff = -0.5f / (spacing * spacing);
    float xc = fminf(d * 0.2f, 1.0f);
    float fcut = (xc < 1.0f) ? 0.5f * (cospif(xc) + 1.0f) : 0.0f;

    float4 acc0 = make_float4(0.f, 0.f, 0.f, 0.f), acc1 = acc0, acc2 = acc0;
    if (fcut > 0.0f) {
        int k0 = (int)rintf(d / spacing);
        int lo = max(0, k0 - 8), hi = min(63, k0 + 8);
        const float4* fw4 = (const float4*)fw;   // 96 float4 per RBF row
        for (int k = lo; k <= hi; k++) {
            float t = d - (float)k * spacing;
            float p = expf(coeff * t * t);
            float4 w0 = fw4[k * 96 + lane];
            float4 w1 = fw4[k * 96 + lane + 32];
            float4 w2 = fw4[k * 96 + lane + 64];
            acc0.x += p * w0.x; acc0.y += p * w0.y; acc0.z += p * w0.z; acc0.w += p * w0.w;
            acc1.x += p * w1.x; acc1.y += p * w1.y; acc1.z += p * w1.z; acc1.w += p * w1.w;
            acc2.x += p * w2.x; acc2.y += p * w2.y; acc2.z += p * w2.z; acc2.w += p * w2.w;
        }
    }
    const float4* fb4 = (const float4*)fb;
    float4* out4 = (float4*)(g_filters + (size_t)e * DD3);
#pragma unroll
    for (int g = 0; g < 3; g++) {
        float4 a = (g == 0) ? acc0 : ((g == 1) ? acc1 : acc2);
        float4 b = fb4[lane + 32 * g];
        float4 v;
        v.x = clip5((a.x + b.x) * fcut);
        v.y = clip5((a.y + b.y) * fcut);
        v.z = clip5((a.z + b.z) * fcut);
        v.w = clip5((a.w + b.w) * fcut);
        out4[lane + 32 * g] = v;
    }
}

// ---------------- edge message scatter: q[i] += dq ; dmu[i] += dmuR*dir + dmumu*mu[j] ----------------
__global__ __launch_bounds__(128) void scatter_msg(const int* __restrict__ ei)
{
    int e = blockIdx.x;
    int c = threadIdx.x;
    int i = ei[e], j = ei[NE + e];
    const float* f  = g_filters + (size_t)e * DD3;
    const float* xj = g_x + (size_t)j * DD3;
    float dq    = xj[c]          * f[c];
    float dmuR  = xj[DD + c]     * f[DD + c];
    float dmumu = xj[2 * DD + c] * f[2 * DD + c];
    atomicAdd(&g_q[(size_t)i * DD + c], dq);
    float d0 = g_dir[(size_t)e * 4 + 0];
    float d1 = g_dir[(size_t)e * 4 + 1];
    float d2 = g_dir[(size_t)e * 4 + 2];
    const float* muj = g_mu + (size_t)j * DD3;
    float* out = g_dmu + (size_t)i * DD3;
    atomicAdd(&out[c],          dmuR * d0 + dmumu * muj[c]);
    atomicAdd(&out[DD + c],     dmuR * d1 + dmumu * muj[DD + c]);
    atomicAdd(&out[2 * DD + c], dmuR * d2 + dmumu * muj[2 * DD + c]);
}

__global__ void merge_mu()
{
    int idx = blockIdx.x * blockDim.x + threadIdx.x;
    if (idx < NN * DD3) { g_mu[idx] += g_dmu[idx]; g_dmu[idx] = 0.f; }
}

// ---------------- mu_Vn / dot(mu_V,mu_W) / ctx ----------------
__global__ __launch_bounds__(128) void reduce_mix()
{
    int n = blockIdx.x, c = threadIdx.x;
    size_t base = (size_t)n * 768;
    float v0 = g_mumix[base + c],        w0 = g_mumix[base + 128 + c];
    float v1 = g_mumix[base + 256 + c],  w1 = g_mumix[base + 384 + c];
    float v2 = g_mumix[base + 512 + c],  w2 = g_mumix[base + 640 + c];
    float vn = sqrtf(v0 * v0 + v1 * v1 + v2 * v2 + 1e-8f);
    g_ctx[(size_t)n * 256 + c]       = g_q[(size_t)n * DD + c];
    g_ctx[(size_t)n * 256 + 128 + c] = vn;
    g_dot[(size_t)n * DD + c] = v0 * w0 + v1 * w1 + v2 * w2;
}

// ---------------- q,mu self-update ----------------
__global__ __launch_bounds__(128) void update_node()
{
    int n = blockIdx.x, c = threadIdx.x;
    size_t xb = (size_t)n * DD3;
    float dq_i  = g_xm[xb + c];
    float dmu_i = g_xm[xb + DD + c];
    float dqmu  = g_xm[xb + 2 * DD + c];
    g_q[(size_t)n * DD + c] += dq_i + dqmu * g_dot[(size_t)n * DD + c];
    size_t mb = (size_t)n * 768;
#pragma unroll
    for (int a = 0; a < 3; a++)
        g_mu[(size_t)n * DD3 + a * DD + c] += dmu_i * g_mumix[mb + a * 256 + 128 + c];
}

// ---------------- final: layernorm(clip(q)) -> tanh -> out ----------------
__global__ __launch_bounds__(128) void layernorm_out(const float* __restrict__ lng,
                                                     const float* __restrict__ lnb,
                                                     float* __restrict__ out)
{
    int n = blockIdx.x, c = threadIdx.x;
    float v = clip5(g_q[(size_t)n * DD + c]);
    float s = v, s2 = v * v;
#pragma unroll
    for (int o = 16; o; o >>= 1) {
        s  += __shfl_xor_sync(0xffffffffu, s, o);
        s2 += __shfl_xor_sync(0xffffffffu, s2, o);
    }
    __shared__ float sh[4], sh2[4];
    int w = c >> 5, l = c & 31;
    if (l == 0) { sh[w] = s; sh2[w] = s2; }
    __syncthreads();
    float S  = sh[0] + sh[1] + sh[2] + sh[3];
    float S2 = sh2[0] + sh2[1] + sh2[2] + sh2[3];
    float mean = S * (1.0f / 128.0f);
    float var  = S2 * (1.0f / 128.0f) - mean * mean;
    float y = (v - mean) * rsqrtf(var + 1e-5f) * lng[c] + lnb[c];
    out[(size_t)n * DD + c] = tanhf(y);
}

// ---------------- final mu_node scatter + pos_attr ----------------
__global__ __launch_bounds__(128) void final_scatter(const int* __restrict__ ei)
{
    int e = blockIdx.x, c = threadIdx.x;
    int i = ei[e], j = ei[NE + e];
    const float* muj = g_mu + (size_t)j * DD3;
    float* out = g_munode + (size_t)i * DD3;
    atomicAdd(&out[c],          muj[c]);
    atomicAdd(&out[DD + c],     muj[DD + c]);
    atomicAdd(&out[2 * DD + c], muj[2 * DD + c]);
}

__global__ __launch_bounds__(128) void pos_out(const float* __restrict__ mpw,
                                               float* __restrict__ out)
{
    int n = blockIdx.x, c = threadIdx.x;
    float w = mpw[c];
    float s0 = clip5(g_munode[(size_t)n * DD3 + c]) * w;
    float s1 = clip5(g_munode[(size_t)n * DD3 + DD + c]) * w;
    float s2 = clip5(g_munode[(size_t)n * DD3 + 2 * DD + c]) * w;
#pragma unroll
    for (int o = 16; o; o >>= 1) {
        s0 += __shfl_xor_sync(0xffffffffu, s0, o);
        s1 += __shfl_xor_sync(0xffffffffu, s1, o);
        s2 += __shfl_xor_sync(0xffffffffu, s2, o);
    }
    __shared__ float sh[4][3];
    int wd = c >> 5, l = c & 31;
    if (l == 0) { sh[wd][0] = s0; sh[wd][1] = s1; sh[wd][2] = s2; }
    __syncthreads();
    if (c < 3) {
        float s = sh[0][c] + sh[1][c] + sh[2][c] + sh[3][c];
        out[(size_t)n * 3 + c] = clip5(s);
    }
}

// ---------------- launch ----------------
extern "C" void kernel_launch(void* const* d_in, const int* in_sizes, int n_in,
                              void* d_out, int out_size)
{
    const float* z      = (const float*)d_in[0];
    const float* pos    = (const float*)d_in[1];
    const int*   ei     = (const int*)  d_in[2];
    const float* in_w   = (const float*)d_in[3];
    const float* in_b   = (const float*)d_in[4];
    const float* filt_w = (const float*)d_in[5];
    const float* filt_b = (const float*)d_in[6];
    const float* iw1    = (const float*)d_in[7];
    const float* ib1    = (const float*)d_in[8];
    const float* iw2    = (const float*)d_in[9];
    const float* ib2    = (const float*)d_in[10];
    const float* mmw    = (const float*)d_in[11];
    const float* mw1    = (const float*)d_in[12];
    const float* mb1    = (const float*)d_in[13];
    const float* mw2    = (const float*)d_in[14];
    const float* mb2    = (const float*)d_in[15];
    const float* mpw    = (const float*)d_in[16];
    const float* lng    = (const float*)d_in[17];
    const float* lnb    = (const float*)d_in[18];
    float* out = (float*)d_out;

    float *p_q, *p_h, *p_x, *p_mu, *p_mumix, *p_ctx, *p_xm;
    cudaGetSymbolAddress((void**)&p_q,     g_q);
    cudaGetSymbolAddress((void**)&p_h,     g_h);
    cudaGetSymbolAddress((void**)&p_x,     g_x);
    cudaGetSymbolAddress((void**)&p_mu,    g_mu);
    cudaGetSymbolAddress((void**)&p_mumix, g_mumix);
    cudaGetSymbolAddress((void**)&p_ctx,   g_ctx);
    cudaGetSymbolAddress((void**)&p_xm,    g_xm);

    int gy_n  = (NN + 127) / 128;        // 157
    int gy_3n = (3 * NN + 127) / 128;    // 469

    zero_bufs<<<(NN * DD3 + 255) / 256, 256>>>();
    sgemm<1><<<dim3(1, gy_n), 256>>>(z, in_w, in_b, p_q, NN, 64, DD);
    edge_pre<<<(NE + 7) / 8, 256>>>(pos, ei, filt_w, filt_b);

    for (int l = 0; l < LNUM; l++) {
        sgemm<1><<<dim3(1, gy_n), 256>>>(p_q, iw1 + (size_t)l * DD * DD, ib1 + (size_t)l * DD,
                                         p_h, NN, DD, DD);
        sgemm<0><<<dim3(3, gy_n), 256>>>(p_h, iw2 + (size_t)l * DD * DD3, ib2 + (size_t)l * DD3,
                                         p_x, NN, DD, DD3);
        scatter_msg<<<NE, 128>>>(ei);
        merge_mu<<<(NN * DD3 + 255) / 256, 256>>>();
        sgemm<0><<<dim3(2, gy_3n), 256>>>(p_mu, mmw + (size_t)l * DD * 256, nullptr,
                                          p_mumix, 3 * NN, DD, 256);
        reduce_mix<<<NN, 128>>>();
        sgemm<1><<<dim3(1, gy_n), 256>>>(p_ctx, mw1 + (size_t)l * 256 * DD, mb1 + (size_t)l * DD,
                                         p_h, NN, 256, DD);
        sgemm<0><<<dim3(3, gy_n), 256>>>(p_h, mw2 + (size_t)l * DD * DD3, mb2 + (size_t)l * DD3,
                                         p_xm, NN, DD, DD3);
        update_node<<<NN, 128>>>();
    }

    layernorm_out<<<NN, 128>>>(lng, lnb, out);
    final_scatter<<<NE, 128>>>(ei);
    pos_out<<<NN, 128>>>(mpw, out + (size_t)NN * DD);
}

// round 2
// speedup vs baseline: 1.1133x; 1.1133x over previous
#include <cuda_runtime.h>
#include <math.h>

#define NN 20000
#define NE 320000
#define DD 128
#define DD3 384
#define LNUM 3

// ---------------- scratch (static device globals) ----------------
__device__ float g_filters[(size_t)NE * DD3];   // 491.5 MB
__device__ float g_dir[(size_t)NE * 4];
__device__ float g_q[(size_t)NN * DD];
__device__ float g_h[(size_t)NN * DD];
__device__ float g_x[(size_t)NN * DD3];
__device__ float g_mu[(size_t)NN * DD3];
__device__ float g_mu2[(size_t)NN * DD3];
__device__ float g_mumix[(size_t)NN * 768];
__device__ float g_ctx[(size_t)NN * 256];
__device__ float g_dot[(size_t)NN * DD];
__device__ float g_xm[(size_t)NN * DD3];
// CSR of incoming edges per destination node i
__device__ int g_cnt[NN];
__device__ int g_rowptr[NN + 1];
__device__ int g_eid[NE];

__device__ __forceinline__ float siluf(float x) { return x / (1.0f + expf(-x)); }
__device__ __forceinline__ float clip5(float x) { return fminf(fmaxf(x, -5.0f), 5.0f); }

// ---------------- SGEMM: C = act(A[M,K] @ B[K,Nc] + bias) ----------------
// BM=64, BN=128, BK=16, 256 threads, 4x8 per thread. K%16==0, Nc%128==0.
template<int ACT>
__global__ __launch_bounds__(256) void sgemm(const float* __restrict__ A,
                                             const float* __restrict__ B,
                                             const float* __restrict__ bias,
                                             float* __restrict__ C,
                                             int M, int K, int Nc)
{
    __shared__ float As[16][64];
    __shared__ float Bs[16][128];
    int tid = threadIdx.x;
    int tx = tid & 15, ty = tid >> 4;
    int row0 = blockIdx.y * 64, col0 = blockIdx.x * 128;
    int arow = tid >> 2, acol = (tid & 3) * 4;
    int brow = tid >> 5, bcol = (tid & 31) * 4;

    float acc[4][8];
#pragma unroll
    for (int i = 0; i < 4; i++)
#pragma unroll
        for (int j = 0; j < 8; j++) acc[i][j] = 0.0f;

    for (int k0 = 0; k0 < K; k0 += 16) {
        float4 av = make_float4(0.f, 0.f, 0.f, 0.f);
        int ar = row0 + arow;
        if (ar < M) av = *(const float4*)(A + (size_t)ar * K + k0 + acol);
        As[acol + 0][arow] = av.x; As[acol + 1][arow] = av.y;
        As[acol + 2][arow] = av.z; As[acol + 3][arow] = av.w;
        float4 b0 = *(const float4*)(B + (size_t)(k0 + brow) * Nc + col0 + bcol);
        float4 b1 = *(const float4*)(B + (size_t)(k0 + brow + 8) * Nc + col0 + bcol);
        *(float4*)(&Bs[brow][bcol]) = b0;
        *(float4*)(&Bs[brow + 8][bcol]) = b1;
        __syncthreads();
#pragma unroll
        for (int k = 0; k < 16; k++) {
            float a[4], b[8];
            *(float4*)(a)     = *(const float4*)(&As[k][ty * 4]);
            *(float4*)(b)     = *(const float4*)(&Bs[k][tx * 8]);
            *(float4*)(b + 4) = *(const float4*)(&Bs[k][tx * 8 + 4]);
#pragma unroll
            for (int i = 0; i < 4; i++)
#pragma unroll
                for (int j = 0; j < 8; j++) acc[i][j] += a[i] * b[j];
        }
        __syncthreads();
    }

#pragma unroll
    for (int i = 0; i < 4; i++) {
        int r = row0 + ty * 4 + i;
        if (r >= M) continue;
#pragma unroll
        for (int jj = 0; jj < 2; jj++) {
            int cb = col0 + tx * 8 + jj * 4;
            float v0 = acc[i][jj * 4 + 0], v1 = acc[i][jj * 4 + 1];
            float v2 = acc[i][jj * 4 + 2], v3 = acc[i][jj * 4 + 3];
            if (bias) { v0 += bias[cb]; v1 += bias[cb + 1]; v2 += bias[cb + 2]; v3 += bias[cb + 3]; }
            if (ACT == 1) { v0 = siluf(v0); v1 = siluf(v1); v2 = siluf(v2); v3 = siluf(v3); }
            *(float4*)(C + (size_t)r * Nc + cb) = make_float4(v0, v1, v2, v3);
        }
    }
}

// ---------------- init: zero mu + CSR counters ----------------
__global__ void init_bufs()
{
    int idx = blockIdx.x * blockDim.x + threadIdx.x;
    if (idx < NN * DD3) g_mu[idx] = 0.f;
    if (idx < NN) g_cnt[idx] = 0;
}

__global__ void csr_count(const int* __restrict__ ei)
{
    int e = blockIdx.x * blockDim.x + threadIdx.x;
    if (e < NE) atomicAdd(&g_cnt[ei[e]], 1);
}

// single block, 1024 threads: exclusive scan of g_cnt -> g_rowptr; reset g_cnt.
__global__ __launch_bounds__(1024) void csr_scan()
{
    __shared__ int part[1024];
    int t = threadIdx.x;
    const int CH = (NN + 1023) / 1024;  // 20
    int base = t * CH;
    int s = 0;
    for (int k = 0; k < CH; k++) {
        int n = base + k;
        if (n < NN) s += g_cnt[n];
    }
    part[t] = s;
    __syncthreads();
    for (int off = 1; off < 1024; off <<= 1) {
        int v = (t >= off) ? part[t - off] : 0;
        __syncthreads();
        part[t] += v;
        __syncthreads();
    }
    int run = (t == 0) ? 0 : part[t - 1];
    for (int k = 0; k < CH; k++) {
        int n = base + k;
        if (n < NN) {
            g_rowptr[n] = run;
            run += g_cnt[n];
            g_cnt[n] = 0;
        }
    }
    if (t == 1023) g_rowptr[NN] = run;
}

__global__ void csr_fill(const int* __restrict__ ei)
{
    int e = blockIdx.x * blockDim.x + threadIdx.x;
    if (e < NE) {
        int i = ei[e];
        int pos = atomicAdd(&g_cnt[i], 1);
        g_eid[g_rowptr[i] + pos] = e;
    }
}

// ---------------- per-edge geometry + RBF filters (truncated Gaussian window) ----------------
__global__ __launch_bounds__(256) void edge_pre(const float* __restrict__ pos,
                                                const int* __restrict__ ei,
                                                const float* __restrict__ fw,
                                                const float* __restrict__ fb)
{
    int e = blockIdx.x * 8 + (threadIdx.x >> 5);
    if (e >= NE) return;
    int lane = threadIdx.x & 31;
    int i = ei[e], j = ei[NE + e];
    float rx = pos[j * 3 + 0] - pos[i * 3 + 0];
    float ry = pos[j * 3 + 1] - pos[i * 3 + 1];
    float rz = pos[j * 3 + 2] - pos[i * 3 + 2];
    float d = sqrtf(rx * rx + ry * ry + rz * rz);
    d = fmaxf(d, 1e-8f);
    float dv = (lane == 0) ? rx : ((lane == 1) ? ry : rz);
    if (lane < 3) g_dir[(size_t)e * 4 + lane] = dv / d;
    if (lane == 3) g_dir[(size_t)e * 4 + 3] = 0.f;

    const float spacing = 5.0f / 63.0f;
    const float coeff = -0.5f / (spacing * spacing);
    float xc = fminf(d * 0.2f, 1.0f);
    float fcut = (xc < 1.0f) ? 0.5f * (cospif(xc) + 1.0f) : 0.0f;

    float4 acc0 = make_float4(0.f, 0.f, 0.f, 0.f), acc1 = acc0, acc2 = acc0;
    if (fcut > 0.0f) {
        int k0 = (int)rintf(d / spacing);
        int lo = max(0, k0 - 8), hi = min(63, k0 + 8);
        const float4* fw4 = (const float4*)fw;
        for (int k = lo; k <= hi; k++) {
            float t = d - (float)k * spacing;
            float p = expf(coeff * t * t);
            float4 w0 = fw4[k * 96 + lane];
            float4 w1 = fw4[k * 96 + lane + 32];
            float4 w2 = fw4[k * 96 + lane + 64];
            acc0.x += p * w0.x; acc0.y += p * w0.y; acc0.z += p * w0.z; acc0.w += p * w0.w;
            acc1.x += p * w1.x; acc1.y += p * w1.y; acc1.z += p * w1.z; acc1.w += p * w1.w;
            acc2.x += p * w2.x; acc2.y += p * w2.y; acc2.z += p * w2.z; acc2.w += p * w2.w;
        }
    }
    const float4* fb4 = (const float4*)fb;
    float4* out4 = (float4*)(g_filters + (size_t)e * DD3);
#pragma unroll
    for (int g = 0; g < 3; g++) {
        float4 a = (g == 0) ? acc0 : ((g == 1) ? acc1 : acc2);
        float4 b = fb4[lane + 32 * g];
        float4 v;
        v.x = clip5((a.x + b.x) * fcut);
        v.y = clip5((a.y + b.y) * fcut);
        v.z = clip5((a.z + b.z) * fcut);
        v.w = clip5((a.w + b.w) * fcut);
        out4[lane + 32 * g] = v;
    }
}

// ---------------- CSR gather of edge messages (no atomics) ----------------
// block = destination node i, 128 threads = channel c.
// q[i] += sum_e dq ; mu_out[i] = mu_in[i] + sum_e (dmuR*dir + dmumu*mu_in[j])
__global__ __launch_bounds__(128) void gather_msg(const int* __restrict__ ei,
                                                  const float* __restrict__ mu_in,
                                                  float* __restrict__ mu_out)
{
    int n = blockIdx.x, c = threadIdx.x;
    int s = g_rowptr[n], t = g_rowptr[n + 1];
    float aq = 0.f, m0 = 0.f, m1 = 0.f, m2 = 0.f;
    for (int k = s; k < t; k++) {
        int e = g_eid[k];
        int j = ei[NE + e];
        const float* f  = g_filters + (size_t)e * DD3;
        const float* xj = g_x + (size_t)j * DD3;
        float dq    = xj[c]          * f[c];
        float dmuR  = xj[DD + c]     * f[DD + c];
        float dmumu = xj[2 * DD + c] * f[2 * DD + c];
        float4 dv = *(const float4*)(g_dir + (size_t)e * 4);
        const float* muj = mu_in + (size_t)j * DD3;
        aq += dq;
        m0 += dmuR * dv.x + dmumu * muj[c];
        m1 += dmuR * dv.y + dmumu * muj[DD + c];
        m2 += dmuR * dv.z + dmumu * muj[2 * DD + c];
    }
    g_q[(size_t)n * DD + c] += aq;
    const float* mui = mu_in + (size_t)n * DD3;
    float* muo = mu_out + (size_t)n * DD3;
    muo[c]          = mui[c] + m0;
    muo[DD + c]     = mui[DD + c] + m1;
    muo[2 * DD + c] = mui[2 * DD + c] + m2;
}

// ---------------- mu_Vn / dot(mu_V,mu_W) / ctx ----------------
__global__ __launch_bounds__(128) void reduce_mix()
{
    int n = blockIdx.x, c = threadIdx.x;
    size_t base = (size_t)n * 768;
    float v0 = g_mumix[base + c],        w0 = g_mumix[base + 128 + c];
    float v1 = g_mumix[base + 256 + c],  w1 = g_mumix[base + 384 + c];
    float v2 = g_mumix[base + 512 + c],  w2 = g_mumix[base + 640 + c];
    float vn = sqrtf(v0 * v0 + v1 * v1 + v2 * v2 + 1e-8f);
    g_ctx[(size_t)n * 256 + c]       = g_q[(size_t)n * DD + c];
    g_ctx[(size_t)n * 256 + 128 + c] = vn;
    g_dot[(size_t)n * DD + c] = v0 * w0 + v1 * w1 + v2 * w2;
}

// ---------------- q,mu self-update ----------------
__global__ __launch_bounds__(128) void update_node(float* __restrict__ mu)
{
    int n = blockIdx.x, c = threadIdx.x;
    size_t xb = (size_t)n * DD3;
    float dq_i  = g_xm[xb + c];
    float dmu_i = g_xm[xb + DD + c];
    float dqmu  = g_xm[xb + 2 * DD + c];
    g_q[(size_t)n * DD + c] += dq_i + dqmu * g_dot[(size_t)n * DD + c];
    size_t mb = (size_t)n * 768;
#pragma unroll
    for (int a = 0; a < 3; a++)
        mu[(size_t)n * DD3 + a * DD + c] += dmu_i * g_mumix[mb + a * 256 + 128 + c];
}

// ---------------- final: layernorm(clip(q)) -> tanh -> out ----------------
__global__ __launch_bounds__(128) void layernorm_out(const float* __restrict__ lng,
                                                     const float* __restrict__ lnb,
                                                     float* __restrict__ out)
{
    int n = blockIdx.x, c = threadIdx.x;
    float v = clip5(g_q[(size_t)n * DD + c]);
    float s = v, s2 = v * v;
#pragma unroll
    for (int o = 16; o; o >>= 1) {
        s  += __shfl_xor_sync(0xffffffffu, s, o);
        s2 += __shfl_xor_sync(0xffffffffu, s2, o);
    }
    __shared__ float sh[4], sh2[4];
    int w = c >> 5, l = c & 31;
    if (l == 0) { sh[w] = s; sh2[w] = s2; }
    __syncthreads();
    float S  = sh[0] + sh[1] + sh[2] + sh[3];
    float S2 = sh2[0] + sh2[1] + sh2[2] + sh2[3];
    float mean = S * (1.0f / 128.0f);
    float var  = S2 * (1.0f / 128.0f) - mean * mean;
    float y = (v - mean) * rsqrtf(var + 1e-5f) * lng[c] + lnb[c];
    out[(size_t)n * DD + c] = tanhf(y);
}

// ---------------- final mu_node gather + pos_attr (fused) ----------------
__global__ __launch_bounds__(128) void pos_gather(const int* __restrict__ ei,
                                                  const float* __restrict__ mu,
                                                  const float* __restrict__ mpw,
                                                  float* __restrict__ out)
{
    int n = blockIdx.x, c = threadIdx.x;
    int s = g_rowptr[n], t = g_rowptr[n + 1];
    float s0 = 0.f, s1 = 0.f, s2 = 0.f;
    for (int k = s; k < t; k++) {
        int e = g_eid[k];
        int j = ei[NE + e];
        const float* muj = mu + (size_t)j * DD3;
        s0 += muj[c];
        s1 += muj[DD + c];
        s2 += muj[2 * DD + c];
    }
    float w = mpw[c];
    s0 = clip5(s0) * w;
    s1 = clip5(s1) * w;
    s2 = clip5(s2) * w;
#pragma unroll
    for (int o = 16; o; o >>= 1) {
        s0 += __shfl_xor_sync(0xffffffffu, s0, o);
        s1 += __shfl_xor_sync(0xffffffffu, s1, o);
        s2 += __shfl_xor_sync(0xffffffffu, s2, o);
    }
    __shared__ float sh[4][3];
    int wd = c >> 5, l = c & 31;
    if (l == 0) { sh[wd][0] = s0; sh[wd][1] = s1; sh[wd][2] = s2; }
    __syncthreads();
    if (c < 3) {
        float v = sh[0][c] + sh[1][c] + sh[2][c] + sh[3][c];
        out[(size_t)n * 3 + c] = clip5(v);
    }
}

// ---------------- launch ----------------
extern "C" void kernel_launch(void* const* d_in, const int* in_sizes, int n_in,
                              void* d_out, int out_size)
{
    const float* z      = (const float*)d_in[0];
    const float* pos    = (const float*)d_in[1];
    const int*   ei     = (const int*)  d_in[2];
    const float* in_w   = (const float*)d_in[3];
    const float* in_b   = (const float*)d_in[4];
    const float* filt_w = (const float*)d_in[5];
    const float* filt_b = (const float*)d_in[6];
    const float* iw1    = (const float*)d_in[7];
    const float* ib1    = (const float*)d_in[8];
    const float* iw2    = (const float*)d_in[9];
    const float* ib2    = (const float*)d_in[10];
    const float* mmw    = (const float*)d_in[11];
    const float* mw1    = (const float*)d_in[12];
    const float* mb1    = (const float*)d_in[13];
    const float* mw2    = (const float*)d_in[14];
    const float* mb2    = (const float*)d_in[15];
    const float* mpw    = (const float*)d_in[16];
    const float* lng    = (const float*)d_in[17];
    const float* lnb    = (const float*)d_in[18];
    float* out = (float*)d_out;

    float *p_q, *p_x, *p_h, *p_mu, *p_mu2, *p_mumix, *p_ctx, *p_xm;
    cudaGetSymbolAddress((void**)&p_q,     g_q);
    cudaGetSymbolAddress((void**)&p_h,     g_h);
    cudaGetSymbolAddress((void**)&p_x,     g_x);
    cudaGetSymbolAddress((void**)&p_mu,    g_mu);
    cudaGetSymbolAddress((void**)&p_mu2,   g_mu2);
    cudaGetSymbolAddress((void**)&p_mumix, g_mumix);
    cudaGetSymbolAddress((void**)&p_ctx,   g_ctx);
    cudaGetSymbolAddress((void**)&p_xm,    g_xm);

    int gy_n  = (NN + 63) / 64;          // 313
    int gy_3n = (3 * NN + 63) / 64;      // 938

    init_bufs<<<(NN * DD3 + 255) / 256, 256>>>();
    csr_count<<<(NE + 255) / 256, 256>>>(ei);
    csr_scan<<<1, 1024>>>();
    csr_fill<<<(NE + 255) / 256, 256>>>(ei);

    sgemm<1><<<dim3(1, gy_n), 256>>>(z, in_w, in_b, p_q, NN, 64, DD);
    edge_pre<<<(NE + 7) / 8, 256>>>(pos, ei, filt_w, filt_b);

    float* mu_in = p_mu;
    float* mu_out = p_mu2;
    for (int l = 0; l < LNUM; l++) {
        sgemm<1><<<dim3(1, gy_n), 256>>>(p_q, iw1 + (size_t)l * DD * DD, ib1 + (size_t)l * DD,
                                         p_h, NN, DD, DD);
        sgemm<0><<<dim3(3, gy_n), 256>>>(p_h, iw2 + (size_t)l * DD * DD3, ib2 + (size_t)l * DD3,
                                         p_x, NN, DD, DD3);
        gather_msg<<<NN, 128>>>(ei, mu_in, mu_out);
        sgemm<0><<<dim3(2, gy_3n), 256>>>(mu_out, mmw + (size_t)l * DD * 256, nullptr,
                                          p_mumix, 3 * NN, DD, 256);
        reduce_mix<<<NN, 128>>>();
        sgemm<1><<<dim3(1, gy_n), 256>>>(p_ctx, mw1 + (size_t)l * 256 * DD, mb1 + (size_t)l * DD,
                                         p_h, NN, 256, DD);
        sgemm<0><<<dim3(3, gy_n), 256>>>(p_h, mw2 + (size_t)l * DD * DD3, mb2 + (size_t)l * DD3,
                                         p_xm, NN, DD, DD3);
        update_node<<<NN, 128>>>(mu_out);
        float* tmp = mu_in; mu_in = mu_out; mu_out = tmp;
    }

    layernorm_out<<<NN, 128>>>(lng, lnb, out);
    pos_gather<<<NN, 128>>>(ei, mu_in, mpw, out + (size_t)NN * DD);
}

// round 3
// speedup vs baseline: 1.1383x; 1.0224x over previous
#include <cuda_runtime.h>
#include <math.h>

#define NN 20000
#define NE 320000
#define DD 128
#define DD3 384
#define LNUM 3

// ---------------- scratch (static device globals) ----------------
__device__ float g_filters[(size_t)NE * DD3];   // CSR-permuted, 491.5 MB
__device__ float g_dir[(size_t)NE * 4];         // CSR-permuted
__device__ int   g_src[NE];                      // CSR-permuted source node j
__device__ int   g_slot[NE];                     // edge id -> CSR slot
__device__ float g_q[(size_t)NN * DD];
__device__ float g_h[(size_t)NN * DD];
__device__ float g_x[(size_t)NN * DD3];
__device__ float g_mu[(size_t)NN * DD3];
__device__ float g_mu2[(size_t)NN * DD3];
__device__ float g_mumix[(size_t)NN * 768];
__device__ float g_ctx[(size_t)NN * 256];
__device__ float g_dot[(size_t)NN * DD];
__device__ float g_xm[(size_t)NN * DD3];
__device__ int g_cnt[NN];
__device__ int g_rowptr[NN + 1];

__device__ __forceinline__ float siluf(float x) { return x / (1.0f + expf(-x)); }
__device__ __forceinline__ float clip5(float x) { return fminf(fmaxf(x, -5.0f), 5.0f); }

// ---------------- SGEMM: C = act(A[M,K] @ B[K,Nc] + bias) ----------------
// BM=64, BN=128, BK=16, 256 threads, 4x8/thread, double-buffered smem.
template<int ACT>
__global__ __launch_bounds__(256) void sgemm(const float* __restrict__ A,
                                             const float* __restrict__ B,
                                             const float* __restrict__ bias,
                                             float* __restrict__ C,
                                             int M, int K, int Nc)
{
    __shared__ float As[2][16][64];
    __shared__ float Bs[2][16][128];
    int tid = threadIdx.x;
    int tx = tid & 15, ty = tid >> 4;
    int row0 = blockIdx.y * 64, col0 = blockIdx.x * 128;
    int arow = tid >> 2, acol = (tid & 3) * 4;
    int brow = tid >> 5, bcol = (tid & 31) * 4;

    bool aval = (row0 + arow) < M;
    const float* Aptr = A + (size_t)(row0 + arow) * K + acol;
    const float* Bptr = B + (size_t)brow * Nc + col0 + bcol;
    size_t bstep8 = (size_t)8 * Nc;

    float acc[4][8];
#pragma unroll
    for (int i = 0; i < 4; i++)
#pragma unroll
        for (int j = 0; j < 8; j++) acc[i][j] = 0.0f;

    // prologue: tile 0 -> buffer 0
    float4 av = make_float4(0.f, 0.f, 0.f, 0.f);
    if (aval) av = *(const float4*)(Aptr);
    float4 b0 = *(const float4*)(Bptr);
    float4 b1 = *(const float4*)(Bptr + bstep8);
    As[0][acol + 0][arow] = av.x; As[0][acol + 1][arow] = av.y;
    As[0][acol + 2][arow] = av.z; As[0][acol + 3][arow] = av.w;
    *(float4*)(&Bs[0][brow][bcol]) = b0;
    *(float4*)(&Bs[0][brow + 8][bcol]) = b1;
    __syncthreads();

    int nt = K >> 4;
    for (int t = 0; t < nt; t++) {
        int cur = t & 1, nxt = cur ^ 1;
        float4 av2, b02, b12;
        if (t + 1 < nt) {
            if (aval) av2 = *(const float4*)(Aptr + (t + 1) * 16);
            else av2 = make_float4(0.f, 0.f, 0.f, 0.f);
            const float* bp = Bptr + (size_t)(t + 1) * 16 * Nc;
            b02 = *(const float4*)(bp);
            b12 = *(const float4*)(bp + bstep8);
        }
#pragma unroll
        for (int k = 0; k < 16; k++) {
            float a[4], b[8];
            *(float4*)(a)     = *(const float4*)(&As[cur][k][ty * 4]);
            *(float4*)(b)     = *(const float4*)(&Bs[cur][k][tx * 8]);
            *(float4*)(b + 4) = *(const float4*)(&Bs[cur][k][tx * 8 + 4]);
#pragma unroll
            for (int i = 0; i < 4; i++)
#pragma unroll
                for (int j = 0; j < 8; j++) acc[i][j] += a[i] * b[j];
        }
        if (t + 1 < nt) {
            As[nxt][acol + 0][arow] = av2.x; As[nxt][acol + 1][arow] = av2.y;
            As[nxt][acol + 2][arow] = av2.z; As[nxt][acol + 3][arow] = av2.w;
            *(float4*)(&Bs[nxt][brow][bcol]) = b02;
            *(float4*)(&Bs[nxt][brow + 8][bcol]) = b12;
        }
        __syncthreads();
    }

#pragma unroll
    for (int i = 0; i < 4; i++) {
        int r = row0 + ty * 4 + i;
        if (r >= M) continue;
#pragma unroll
        for (int jj = 0; jj < 2; jj++) {
            int cb = col0 + tx * 8 + jj * 4;
            float v0 = acc[i][jj * 4 + 0], v1 = acc[i][jj * 4 + 1];
            float v2 = acc[i][jj * 4 + 2], v3 = acc[i][jj * 4 + 3];
            if (bias) { v0 += bias[cb]; v1 += bias[cb + 1]; v2 += bias[cb + 2]; v3 += bias[cb + 3]; }
            if (ACT == 1) { v0 = siluf(v0); v1 = siluf(v1); v2 = siluf(v2); v3 = siluf(v3); }
            *(float4*)(C + (size_t)r * Nc + cb) = make_float4(v0, v1, v2, v3);
        }
    }
}

// ---------------- CSR build ----------------
__global__ void init_bufs()
{
    int idx = blockIdx.x * blockDim.x + threadIdx.x;
    if (idx < NN * DD3) g_mu[idx] = 0.f;
    if (idx < NN) g_cnt[idx] = 0;
}

__global__ void csr_count(const int* __restrict__ ei)
{
    int e = blockIdx.x * blockDim.x + threadIdx.x;
    if (e < NE) atomicAdd(&g_cnt[ei[e]], 1);
}

__global__ __launch_bounds__(1024) void csr_scan()
{
    __shared__ int part[1024];
    int t = threadIdx.x;
    const int CH = (NN + 1023) / 1024;
    int base = t * CH;
    int s = 0;
    for (int k = 0; k < CH; k++) {
        int n = base + k;
        if (n < NN) s += g_cnt[n];
    }
    part[t] = s;
    __syncthreads();
    for (int off = 1; off < 1024; off <<= 1) {
        int v = (t >= off) ? part[t - off] : 0;
        __syncthreads();
        part[t] += v;
        __syncthreads();
    }
    int run = (t == 0) ? 0 : part[t - 1];
    for (int k = 0; k < CH; k++) {
        int n = base + k;
        if (n < NN) {
            g_rowptr[n] = run;
            run += g_cnt[n];
            g_cnt[n] = 0;
        }
    }
    if (t == 1023) g_rowptr[NN] = run;
}

__global__ void csr_fill(const int* __restrict__ ei)
{
    int e = blockIdx.x * blockDim.x + threadIdx.x;
    if (e < NE) {
        int i = ei[e];
        int pos = atomicAdd(&g_cnt[i], 1);
        int slot = g_rowptr[i] + pos;
        g_slot[e] = slot;
        g_src[slot] = ei[NE + e];
    }
}

// ---------------- per-edge geometry + RBF filters, written to CSR slot ----------------
__global__ __launch_bounds__(256) void edge_pre(const float* __restrict__ pos,
                                                const int* __restrict__ ei,
                                                const float* __restrict__ fw,
                                                const float* __restrict__ fb)
{
    int e = blockIdx.x * 8 + (threadIdx.x >> 5);
    if (e >= NE) return;
    int lane = threadIdx.x & 31;
    int i = ei[e], j = ei[NE + e];
    int slot = g_slot[e];
    float rx = pos[j * 3 + 0] - pos[i * 3 + 0];
    float ry = pos[j * 3 + 1] - pos[i * 3 + 1];
    float rz = pos[j * 3 + 2] - pos[i * 3 + 2];
    float d = sqrtf(rx * rx + ry * ry + rz * rz);
    d = fmaxf(d, 1e-8f);
    float dv = (lane == 0) ? rx : ((lane == 1) ? ry : rz);
    if (lane < 3) g_dir[(size_t)slot * 4 + lane] = dv / d;
    if (lane == 3) g_dir[(size_t)slot * 4 + 3] = 0.f;

    const float spacing = 5.0f / 63.0f;
    const float coeff = -0.5f / (spacing * spacing);
    float xc = fminf(d * 0.2f, 1.0f);
    float fcut = (xc < 1.0f) ? 0.5f * (cospif(xc) + 1.0f) : 0.0f;

    float4 acc0 = make_float4(0.f, 0.f, 0.f, 0.f), acc1 = acc0, acc2 = acc0;
    if (fcut > 0.0f) {
        int k0 = (int)rintf(d / spacing);
        int lo = max(0, k0 - 8), hi = min(63, k0 + 8);
        const float4* fw4 = (const float4*)fw;
        for (int k = lo; k <= hi; k++) {
            float t = d - (float)k * spacing;
            float p = expf(coeff * t * t);
            float4 w0 = fw4[k * 96 + lane];
            float4 w1 = fw4[k * 96 + lane + 32];
            float4 w2 = fw4[k * 96 + lane + 64];
            acc0.x += p * w0.x; acc0.y += p * w0.y; acc0.z += p * w0.z; acc0.w += p * w0.w;
            acc1.x += p * w1.x; acc1.y += p * w1.y; acc1.z += p * w1.z; acc1.w += p * w1.w;
            acc2.x += p * w2.x; acc2.y += p * w2.y; acc2.z += p * w2.z; acc2.w += p * w2.w;
        }
    }
    const float4* fb4 = (const float4*)fb;
    float4* out4 = (float4*)(g_filters + (size_t)slot * DD3);
#pragma unroll
    for (int g = 0; g < 3; g++) {
        float4 a = (g == 0) ? acc0 : ((g == 1) ? acc1 : acc2);
        float4 b = fb4[lane + 32 * g];
        float4 v;
        v.x = clip5((a.x + b.x) * fcut);
        v.y = clip5((a.y + b.y) * fcut);
        v.z = clip5((a.z + b.z) * fcut);
        v.w = clip5((a.w + b.w) * fcut);
        out4[lane + 32 * g] = v;
    }
}

// ---------------- CSR gather of edge messages (sequential filter stream) ----------------
__global__ __launch_bounds__(128) void gather_msg(const float* __restrict__ mu_in,
                                                  float* __restrict__ mu_out)
{
    int n = blockIdx.x, c = threadIdx.x;
    int s = g_rowptr[n], t = g_rowptr[n + 1];
    float aq = 0.f, m0 = 0.f, m1 = 0.f, m2 = 0.f;
    for (int k = s; k < t; k++) {
        int j = __ldg(&g_src[k]);
        const float* f  = g_filters + (size_t)k * DD3;
        const float* xj = g_x + (size_t)j * DD3;
        float dq    = xj[c]          * f[c];
        float dmuR  = xj[DD + c]     * f[DD + c];
        float dmumu = xj[2 * DD + c] * f[2 * DD + c];
        float4 dv = *(const float4*)(g_dir + (size_t)k * 4);
        const float* muj = mu_in + (size_t)j * DD3;
        aq += dq;
        m0 += dmuR * dv.x + dmumu * muj[c];
        m1 += dmuR * dv.y + dmumu * muj[DD + c];
        m2 += dmuR * dv.z + dmumu * muj[2 * DD + c];
    }
    g_q[(size_t)n * DD + c] += aq;
    const float* mui = mu_in + (size_t)n * DD3;
    float* muo = mu_out + (size_t)n * DD3;
    muo[c]          = mui[c] + m0;
    muo[DD + c]     = mui[DD + c] + m1;
    muo[2 * DD + c] = mui[2 * DD + c] + m2;
}

// ---------------- mu_Vn / dot(mu_V,mu_W) / ctx ----------------
__global__ __launch_bounds__(128) void reduce_mix()
{
    int n = blockIdx.x, c = threadIdx.x;
    size_t base = (size_t)n * 768;
    float v0 = g_mumix[base + c],        w0 = g_mumix[base + 128 + c];
    float v1 = g_mumix[base + 256 + c],  w1 = g_mumix[base + 384 + c];
    float v2 = g_mumix[base + 512 + c],  w2 = g_mumix[base + 640 + c];
    float vn = sqrtf(v0 * v0 + v1 * v1 + v2 * v2 + 1e-8f);
    g_ctx[(size_t)n * 256 + c]       = g_q[(size_t)n * DD + c];
    g_ctx[(size_t)n * 256 + 128 + c] = vn;
    g_dot[(size_t)n * DD + c] = v0 * w0 + v1 * w1 + v2 * w2;
}

// ---------------- q,mu self-update ----------------
__global__ __launch_bounds__(128) void update_node(float* __restrict__ mu)
{
    int n = blockIdx.x, c = threadIdx.x;
    size_t xb = (size_t)n * DD3;
    float dq_i  = g_xm[xb + c];
    float dmu_i = g_xm[xb + DD + c];
    float dqmu  = g_xm[xb + 2 * DD + c];
    g_q[(size_t)n * DD + c] += dq_i + dqmu * g_dot[(size_t)n * DD + c];
    size_t mb = (size_t)n * 768;
#pragma unroll
    for (int a = 0; a < 3; a++)
        mu[(size_t)n * DD3 + a * DD + c] += dmu_i * g_mumix[mb + a * 256 + 128 + c];
}

// ---------------- final layernorm -> tanh ----------------
__global__ __launch_bounds__(128) void layernorm_out(const float* __restrict__ lng,
                                                     const float* __restrict__ lnb,
                                                     float* __restrict__ out)
{
    int n = blockIdx.x, c = threadIdx.x;
    float v = clip5(g_q[(size_t)n * DD + c]);
    float s = v, s2 = v * v;
#pragma unroll
    for (int o = 16; o; o >>= 1) {
        s  += __shfl_xor_sync(0xffffffffu, s, o);
        s2 += __shfl_xor_sync(0xffffffffu, s2, o);
    }
    __shared__ float sh[4], sh2[4];
    int w = c >> 5, l = c & 31;
    if (l == 0) { sh[w] = s; sh2[w] = s2; }
    __syncthreads();
    float S  = sh[0] + sh[1] + sh[2] + sh[3];
    float S2 = sh2[0] + sh2[1] + sh2[2] + sh2[3];
    float mean = S * (1.0f / 128.0f);
    float var  = S2 * (1.0f / 128.0f) - mean * mean;
    float y = (v - mean) * rsqrtf(var + 1e-5f) * lng[c] + lnb[c];
    out[(size_t)n * DD + c] = tanhf(y);
}

// ---------------- final mu_node gather + pos_attr (fused) ----------------
__global__ __launch_bounds__(128) void pos_gather(const float* __restrict__ mu,
                                                  const float* __restrict__ mpw,
                                                  float* __restrict__ out)
{
    int n = blockIdx.x, c = threadIdx.x;
    int s = g_rowptr[n], t = g_rowptr[n + 1];
    float s0 = 0.f, s1 = 0.f, s2 = 0.f;
    for (int k = s; k < t; k++) {
        int j = __ldg(&g_src[k]);
        const float* muj = mu + (size_t)j * DD3;
        s0 += muj[c];
        s1 += muj[DD + c];
        s2 += muj[2 * DD + c];
    }
    float w = mpw[c];
    s0 = clip5(s0) * w;
    s1 = clip5(s1) * w;
    s2 = clip5(s2) * w;
#pragma unroll
    for (int o = 16; o; o >>= 1) {
        s0 += __shfl_xor_sync(0xffffffffu, s0, o);
        s1 += __shfl_xor_sync(0xffffffffu, s1, o);
        s2 += __shfl_xor_sync(0xffffffffu, s2, o);
    }
    __shared__ float sh[4][3];
    int wd = c >> 5, l = c & 31;
    if (l == 0) { sh[wd][0] = s0; sh[wd][1] = s1; sh[wd][2] = s2; }
    __syncthreads();
    if (c < 3) {
        float v = sh[0][c] + sh[1][c] + sh[2][c] + sh[3][c];
        out[(size_t)n * 3 + c] = clip5(v);
    }
}

// ---------------- launch ----------------
extern "C" void kernel_launch(void* const* d_in, const int* in_sizes, int n_in,
                              void* d_out, int out_size)
{
    const float* z      = (const float*)d_in[0];
    const float* pos    = (const float*)d_in[1];
    const int*   ei     = (const int*)  d_in[2];
    const float* in_w   = (const float*)d_in[3];
    const float* in_b   = (const float*)d_in[4];
    const float* filt_w = (const float*)d_in[5];
    const float* filt_b = (const float*)d_in[6];
    const float* iw1    = (const float*)d_in[7];
    const float* ib1    = (const float*)d_in[8];
    const float* iw2    = (const float*)d_in[9];
    const float* ib2    = (const float*)d_in[10];
    const float* mmw    = (const float*)d_in[11];
    const float* mw1    = (const float*)d_in[12];
    const float* mb1    = (const float*)d_in[13];
    const float* mw2    = (const float*)d_in[14];
    const float* mb2    = (const float*)d_in[15];
    const float* mpw    = (const float*)d_in[16];
    const float* lng    = (const float*)d_in[17];
    const float* lnb    = (const float*)d_in[18];
    float* out = (float*)d_out;

    float *p_q, *p_x, *p_h, *p_mu, *p_mu2, *p_mumix, *p_ctx, *p_xm;
    cudaGetSymbolAddress((void**)&p_q,     g_q);
    cudaGetSymbolAddress((void**)&p_h,     g_h);
    cudaGetSymbolAddress((void**)&p_x,     g_x);
    cudaGetSymbolAddress((void**)&p_mu,    g_mu);
    cudaGetSymbolAddress((void**)&p_mu2,   g_mu2);
    cudaGetSymbolAddress((void**)&p_mumix, g_mumix);
    cudaGetSymbolAddress((void**)&p_ctx,   g_ctx);
    cudaGetSymbolAddress((void**)&p_xm,    g_xm);

    int gy_n  = (NN + 63) / 64;          // 313
    int gy_3n = (3 * NN + 63) / 64;      // 938

    init_bufs<<<(NN * DD3 + 255) / 256, 256>>>();
    csr_count<<<(NE + 255) / 256, 256>>>(ei);
    csr_scan<<<1, 1024>>>();
    csr_fill<<<(NE + 255) / 256, 256>>>(ei);

    sgemm<1><<<dim3(1, gy_n), 256>>>(z, in_w, in_b, p_q, NN, 64, DD);
    edge_pre<<<(NE + 7) / 8, 256>>>(pos, ei, filt_w, filt_b);

    float* mu_in = p_mu;
    float* mu_out = p_mu2;
    for (int l = 0; l < LNUM; l++) {
        sgemm<1><<<dim3(1, gy_n), 256>>>(p_q, iw1 + (size_t)l * DD * DD, ib1 + (size_t)l * DD,
                                         p_h, NN, DD, DD);
        sgemm<0><<<dim3(3, gy_n), 256>>>(p_h, iw2 + (size_t)l * DD * DD3, ib2 + (size_t)l * DD3,
                                         p_x, NN, DD, DD3);
        gather_msg<<<NN, 128>>>(mu_in, mu_out);
        sgemm<0><<<dim3(2, gy_3n), 256>>>(mu_out, mmw + (size_t)l * DD * 256, nullptr,
                                          p_mumix, 3 * NN, DD, 256);
        reduce_mix<<<NN, 128>>>();
        sgemm<1><<<dim3(1, gy_n), 256>>>(p_ctx, mw1 + (size_t)l * 256 * DD, mb1 + (size_t)l * DD,
                                         p_h, NN, 256, DD);
        sgemm<0><<<dim3(3, gy_n), 256>>>(p_h, mw2 + (size_t)l * DD * DD3, mb2 + (size_t)l * DD3,
                                         p_xm, NN, DD, DD3);
        update_node<<<NN, 128>>>(mu_out);
        float* tmp = mu_in; mu_in = mu_out; mu_out = tmp;
    }

    layernorm_out<<<NN, 128>>>(lng, lnb, out);
    pos_gather<<<NN, 128>>>(mu_in, mpw, out + (size_t)NN * DD);
}

// round 4
// speedup vs baseline: 1.8410x; 1.6173x over previous
#include <cuda_runtime.h>
#include <cuda_fp16.h>
#include <math.h>

#define NN 20000
#define NE 320000
#define DD 128
#define DD3 384
#define LNUM 3

// ---------------- scratch (static device globals) ----------------
__device__ __half g_filters[(size_t)NE * DD3];  // CSR-permuted, fp16, 246 MB
__device__ float g_dir[(size_t)NE * 4];         // CSR-permuted
__device__ int   g_src[NE];                      // CSR-permuted source node j
__device__ int   g_slot[NE];                     // edge id -> CSR slot
__device__ float g_q[(size_t)NN * DD];
__device__ float g_h[(size_t)NN * DD];
__device__ float g_x[(size_t)NN * DD3];
__device__ float g_mu[(size_t)NN * DD3];
__device__ float g_mu2[(size_t)NN * DD3];
__device__ float g_mumix[(size_t)NN * 768];
__device__ float g_ctx[(size_t)NN * 256];
__device__ float g_dot[(size_t)NN * DD];
__device__ float g_xm[(size_t)NN * DD3];
__device__ int g_cnt[NN];
__device__ int g_rowptr[NN + 1];

__device__ __forceinline__ float siluf(float x) { return x / (1.0f + expf(-x)); }
__device__ __forceinline__ float clip5(float x) { return fminf(fmaxf(x, -5.0f), 5.0f); }

__device__ __forceinline__ unsigned f2tf32(float f)
{
    unsigned r;
    asm("cvt.rna.tf32.f32 %0, %1;" : "=r"(r) : "f"(f));
    return r;
}

__device__ __forceinline__ void mma_tf32(float* c, const unsigned* a, const unsigned* b)
{
    asm volatile(
        "mma.sync.aligned.m16n8k8.row.col.f32.tf32.tf32.f32 "
        "{%0,%1,%2,%3}, {%4,%5,%6,%7}, {%8,%9}, {%0,%1,%2,%3};"
        : "+f"(c[0]), "+f"(c[1]), "+f"(c[2]), "+f"(c[3])
        : "r"(a[0]), "r"(a[1]), "r"(a[2]), "r"(a[3]), "r"(b[0]), "r"(b[1]));
}

// ---------------- TF32 tensor-core GEMM: C = act(A[M,K] @ B[K,Nc] + bias) ----------------
// BM=128, BN=128, BK=16. 256 threads = 8 warps in 2(M)x4(N); warp tile 64x32.
// K % 16 == 0, Nc % 128 == 0.
#define AS_STRIDE 20
#define BS_STRIDE 136
template<int ACT>
__global__ __launch_bounds__(256) void tgemm(const float* __restrict__ A,
                                             const float* __restrict__ B,
                                             const float* __restrict__ bias,
                                             float* __restrict__ C,
                                             int M, int K, int Nc)
{
    __shared__ float As[2][128][AS_STRIDE];
    __shared__ float Bs[2][16][BS_STRIDE];
    int tid = threadIdx.x;
    int wid = tid >> 5, lane = tid & 31;
    int g = lane >> 2, tg = lane & 3;
    int wm = wid & 1, wn = wid >> 1;
    int row0 = blockIdx.y * 128, col0 = blockIdx.x * 128;

    int arow = tid >> 1, acol = (tid & 1) * 8;
    int brow = tid >> 4, bcol = (tid & 15) * 8;
    bool aval = (row0 + arow) < M;
    const float* Aptr = A + (size_t)(row0 + arow) * K + acol;
    const float* Bptr = B + (size_t)brow * Nc + col0 + bcol;

    float acc[4][4][4];
#pragma unroll
    for (int mt = 0; mt < 4; mt++)
#pragma unroll
        for (int nt = 0; nt < 4; nt++)
#pragma unroll
            for (int r = 0; r < 4; r++) acc[mt][nt][r] = 0.0f;

    // prologue: tile 0 -> buffer 0
    float4 a0 = make_float4(0.f, 0.f, 0.f, 0.f), a1 = a0;
    if (aval) { a0 = *(const float4*)(Aptr); a1 = *(const float4*)(Aptr + 4); }
    float4 b0 = *(const float4*)(Bptr);
    float4 b1 = *(const float4*)(Bptr + 4);
    *(float4*)(&As[0][arow][acol])     = a0;
    *(float4*)(&As[0][arow][acol + 4]) = a1;
    *(float4*)(&Bs[0][brow][bcol])     = b0;
    *(float4*)(&Bs[0][brow][bcol + 4]) = b1;
    __syncthreads();

    int nt_tiles = K >> 4;
    for (int t = 0; t < nt_tiles; t++) {
        int cur = t & 1, nxt = cur ^ 1;
        float4 na0, na1, nb0, nb1;
        if (t + 1 < nt_tiles) {
            if (aval) {
                na0 = *(const float4*)(Aptr + (t + 1) * 16);
                na1 = *(const float4*)(Aptr + (t + 1) * 16 + 4);
            } else { na0 = make_float4(0.f,0.f,0.f,0.f); na1 = na0; }
            const float* bp = Bptr + (size_t)(t + 1) * 16 * Nc;
            nb0 = *(const float4*)(bp);
            nb1 = *(const float4*)(bp + 4);
        }
#pragma unroll
        for (int kc = 0; kc < 16; kc += 8) {
            unsigned ar[4][4], br[4][2];
#pragma unroll
            for (int mt = 0; mt < 4; mt++) {
                int r = wm * 64 + mt * 16;
                ar[mt][0] = f2tf32(As[cur][r + g][kc + tg]);
                ar[mt][1] = f2tf32(As[cur][r + g + 8][kc + tg]);
                ar[mt][2] = f2tf32(As[cur][r + g][kc + tg + 4]);
                ar[mt][3] = f2tf32(As[cur][r + g + 8][kc + tg + 4]);
            }
#pragma unroll
            for (int nt = 0; nt < 4; nt++) {
                int nc0 = wn * 32 + nt * 8;
                br[nt][0] = f2tf32(Bs[cur][kc + tg][nc0 + g]);
                br[nt][1] = f2tf32(Bs[cur][kc + tg + 4][nc0 + g]);
            }
#pragma unroll
            for (int mt = 0; mt < 4; mt++)
#pragma unroll
                for (int nt = 0; nt < 4; nt++)
                    mma_tf32(acc[mt][nt], ar[mt], br[nt]);
        }
        if (t + 1 < nt_tiles) {
            *(float4*)(&As[nxt][arow][acol])     = na0;
            *(float4*)(&As[nxt][arow][acol + 4]) = na1;
            *(float4*)(&Bs[nxt][brow][bcol])     = nb0;
            *(float4*)(&Bs[nxt][brow][bcol + 4]) = nb1;
        }
        __syncthreads();
    }

    // epilogue
#pragma unroll
    for (int mt = 0; mt < 4; mt++) {
#pragma unroll
        for (int nt = 0; nt < 4; nt++) {
            int col = col0 + wn * 32 + nt * 8 + 2 * tg;
            float bb0 = 0.f, bb1 = 0.f;
            if (bias) { bb0 = bias[col]; bb1 = bias[col + 1]; }
#pragma unroll
            for (int half = 0; half < 2; half++) {
                int row = row0 + wm * 64 + mt * 16 + g + half * 8;
                if (row >= M) continue;
                float v0 = acc[mt][nt][half * 2 + 0] + bb0;
                float v1 = acc[mt][nt][half * 2 + 1] + bb1;
                if (ACT == 1) { v0 = siluf(v0); v1 = siluf(v1); }
                *(float2*)(C + (size_t)row * Nc + col) = make_float2(v0, v1);
            }
        }
    }
}

// ---------------- CSR build ----------------
__global__ void init_bufs()
{
    int idx = blockIdx.x * blockDim.x + threadIdx.x;
    if (idx < NN * DD3) g_mu[idx] = 0.f;
    if (idx < NN) g_cnt[idx] = 0;
}

__global__ void csr_count(const int* __restrict__ ei)
{
    int e = blockIdx.x * blockDim.x + threadIdx.x;
    if (e < NE) atomicAdd(&g_cnt[ei[e]], 1);
}

__global__ __launch_bounds__(1024) void csr_scan()
{
    __shared__ int part[1024];
    int t = threadIdx.x;
    const int CH = (NN + 1023) / 1024;
    int base = t * CH;
    int s = 0;
    for (int k = 0; k < CH; k++) {
        int n = base + k;
        if (n < NN) s += g_cnt[n];
    }
    part[t] = s;
    __syncthreads();
    for (int off = 1; off < 1024; off <<= 1) {
        int v = (t >= off) ? part[t - off] : 0;
        __syncthreads();
        part[t] += v;
        __syncthreads();
    }
    int run = (t == 0) ? 0 : part[t - 1];
    for (int k = 0; k < CH; k++) {
        int n = base + k;
        if (n < NN) {
            g_rowptr[n] = run;
            run += g_cnt[n];
            g_cnt[n] = 0;
        }
    }
    if (t == 1023) g_rowptr[NN] = run;
}

__global__ void csr_fill(const int* __restrict__ ei)
{
    int e = blockIdx.x * blockDim.x + threadIdx.x;
    if (e < NE) {
        int i = ei[e];
        int pos = atomicAdd(&g_cnt[i], 1);
        int slot = g_rowptr[i] + pos;
        g_slot[e] = slot;
        g_src[slot] = ei[NE + e];
    }
}

// ---------------- per-edge geometry + RBF filters (fp16, written to CSR slot) ----------------
__global__ __launch_bounds__(256) void edge_pre(const float* __restrict__ pos,
                                                const int* __restrict__ ei,
                                                const float* __restrict__ fw,
                                                const float* __restrict__ fb)
{
    int e = blockIdx.x * 8 + (threadIdx.x >> 5);
    if (e >= NE) return;
    int lane = threadIdx.x & 31;
    int i = ei[e], j = ei[NE + e];
    int slot = g_slot[e];
    float rx = pos[j * 3 + 0] - pos[i * 3 + 0];
    float ry = pos[j * 3 + 1] - pos[i * 3 + 1];
    float rz = pos[j * 3 + 2] - pos[i * 3 + 2];
    float d = sqrtf(rx * rx + ry * ry + rz * rz);
    d = fmaxf(d, 1e-8f);
    float dv = (lane == 0) ? rx : ((lane == 1) ? ry : rz);
    if (lane < 3) g_dir[(size_t)slot * 4 + lane] = dv / d;
    if (lane == 3) g_dir[(size_t)slot * 4 + 3] = 0.f;

    const float spacing = 5.0f / 63.0f;
    const float coeff = -0.5f / (spacing * spacing);
    float xc = fminf(d * 0.2f, 1.0f);
    float fcut = (xc < 1.0f) ? 0.5f * (cospif(xc) + 1.0f) : 0.0f;

    float4 acc0 = make_float4(0.f, 0.f, 0.f, 0.f), acc1 = acc0, acc2 = acc0;
    if (fcut > 0.0f) {
        int k0 = (int)rintf(d / spacing);
        int lo = max(0, k0 - 8), hi = min(63, k0 + 8);
        const float4* fw4 = (const float4*)fw;
        for (int k = lo; k <= hi; k++) {
            float t = d - (float)k * spacing;
            float p = expf(coeff * t * t);
            float4 w0 = fw4[k * 96 + lane];
            float4 w1 = fw4[k * 96 + lane + 32];
            float4 w2 = fw4[k * 96 + lane + 64];
            acc0.x += p * w0.x; acc0.y += p * w0.y; acc0.z += p * w0.z; acc0.w += p * w0.w;
            acc1.x += p * w1.x; acc1.y += p * w1.y; acc1.z += p * w1.z; acc1.w += p * w1.w;
            acc2.x += p * w2.x; acc2.y += p * w2.y; acc2.z += p * w2.z; acc2.w += p * w2.w;
        }
    }
    const float4* fb4 = (const float4*)fb;
    __half2* outh = (__half2*)(g_filters + (size_t)slot * DD3);
#pragma unroll
    for (int grp = 0; grp < 3; grp++) {
        float4 a = (grp == 0) ? acc0 : ((grp == 1) ? acc1 : acc2);
        float4 b = fb4[lane + 32 * grp];
        float v0 = clip5((a.x + b.x) * fcut);
        float v1 = clip5((a.y + b.y) * fcut);
        float v2 = clip5((a.z + b.z) * fcut);
        float v3 = clip5((a.w + b.w) * fcut);
        int base2 = (grp * 128 + lane * 4) >> 1;   // index in half2 units
        outh[base2]     = __floats2half2_rn(v0, v1);
        outh[base2 + 1] = __floats2half2_rn(v2, v3);
    }
}

// ---------------- CSR gather of edge messages ----------------
__global__ __launch_bounds__(128) void gather_msg(const float* __restrict__ mu_in,
                                                  float* __restrict__ mu_out)
{
    int n = blockIdx.x, c = threadIdx.x;
    int s = g_rowptr[n], t = g_rowptr[n + 1];
    float aq = 0.f, m0 = 0.f, m1 = 0.f, m2 = 0.f;
    for (int k = s; k < t; k++) {
        int j = __ldg(&g_src[k]);
        const __half* f = g_filters + (size_t)k * DD3;
        const float* xj = g_x + (size_t)j * DD3;
        float dq    = xj[c]          * __half2float(f[c]);
        float dmuR  = xj[DD + c]     * __half2float(f[DD + c]);
        float dmumu = xj[2 * DD + c] * __half2float(f[2 * DD + c]);
        float4 dv = *(const float4*)(g_dir + (size_t)k * 4);
        const float* muj = mu_in + (size_t)j * DD3;
        aq += dq;
        m0 += dmuR * dv.x + dmumu * muj[c];
        m1 += dmuR * dv.y + dmumu * muj[DD + c];
        m2 += dmuR * dv.z + dmumu * muj[2 * DD + c];
    }
    g_q[(size_t)n * DD + c] += aq;
    const float* mui = mu_in + (size_t)n * DD3;
    float* muo = mu_out + (size_t)n * DD3;
    muo[c]          = mui[c] + m0;
    muo[DD + c]     = mui[DD + c] + m1;
    muo[2 * DD + c] = mui[2 * DD + c] + m2;
}

// ---------------- mu_Vn / dot(mu_V,mu_W) / ctx ----------------
__global__ __launch_bounds__(128) void reduce_mix()
{
    int n = blockIdx.x, c = threadIdx.x;
    size_t base = (size_t)n * 768;
    float v0 = g_mumix[base + c],        w0 = g_mumix[base + 128 + c];
    float v1 = g_mumix[base + 256 + c],  w1 = g_mumix[base + 384 + c];
    float v2 = g_mumix[base + 512 + c],  w2 = g_mumix[base + 640 + c];
    float vn = sqrtf(v0 * v0 + v1 * v1 + v2 * v2 + 1e-8f);
    g_ctx[(size_t)n * 256 + c]       = g_q[(size_t)n * DD + c];
    g_ctx[(size_t)n * 256 + 128 + c] = vn;
    g_dot[(size_t)n * DD + c] = v0 * w0 + v1 * w1 + v2 * w2;
}

// ---------------- q,mu self-update ----------------
__global__ __launch_bounds__(128) void update_node(float* __restrict__ mu)
{
    int n = blockIdx.x, c = threadIdx.x;
    size_t xb = (size_t)n * DD3;
    float dq_i  = g_xm[xb + c];
    float dmu_i = g_xm[xb + DD + c];
    float dqmu  = g_xm[xb + 2 * DD + c];
    g_q[(size_t)n * DD + c] += dq_i + dqmu * g_dot[(size_t)n * DD + c];
    size_t mb = (size_t)n * 768;
#pragma unroll
    for (int a = 0; a < 3; a++)
        mu[(size_t)n * DD3 + a * DD + c] += dmu_i * g_mumix[mb + a * 256 + 128 + c];
}

// ---------------- final layernorm -> tanh ----------------
__global__ __launch_bounds__(128) void layernorm_out(const float* __restrict__ lng,
                                                     const float* __restrict__ lnb,
                                                     float* __restrict__ out)
{
    int n = blockIdx.x, c = threadIdx.x;
    float v = clip5(g_q[(size_t)n * DD + c]);
    float s = v, s2 = v * v;
#pragma unroll
    for (int o = 16; o; o >>= 1) {
        s  += __shfl_xor_sync(0xffffffffu, s, o);
        s2 += __shfl_xor_sync(0xffffffffu, s2, o);
    }
    __shared__ float sh[4], sh2[4];
    int w = c >> 5, l = c & 31;
    if (l == 0) { sh[w] = s; sh2[w] = s2; }
    __syncthreads();
    float S  = sh[0] + sh[1] + sh[2] + sh[3];
    float S2 = sh2[0] + sh2[1] + sh2[2] + sh2[3];
    float mean = S * (1.0f / 128.0f);
    float var  = S2 * (1.0f / 128.0f) - mean * mean;
    float y = (v - mean) * rsqrtf(var + 1e-5f) * lng[c] + lnb[c];
    out[(size_t)n * DD + c] = tanhf(y);
}

// ---------------- final mu_node gather + pos_attr (fused) ----------------
__global__ __launch_bounds__(128) void pos_gather(const float* __restrict__ mu,
                                                  const float* __restrict__ mpw,
                                                  float* __restrict__ out)
{
    int n = blockIdx.x, c = threadIdx.x;
    int s = g_rowptr[n], t = g_rowptr[n + 1];
    float s0 = 0.f, s1 = 0.f, s2 = 0.f;
    for (int k = s; k < t; k++) {
        int j = __ldg(&g_src[k]);
        const float* muj = mu + (size_t)j * DD3;
        s0 += muj[c];
        s1 += muj[DD + c];
        s2 += muj[2 * DD + c];
    }
    float w = mpw[c];
    s0 = clip5(s0) * w;
    s1 = clip5(s1) * w;
    s2 = clip5(s2) * w;
#pragma unroll
    for (int o = 16; o; o >>= 1) {
        s0 += __shfl_xor_sync(0xffffffffu, s0, o);
        s1 += __shfl_xor_sync(0xffffffffu, s1, o);
        s2 += __shfl_xor_sync(0xffffffffu, s2, o);
    }
    __shared__ float sh[4][3];
    int wd = c >> 5, l = c & 31;
    if (l == 0) { sh[wd][0] = s0; sh[wd][1] = s1; sh[wd][2] = s2; }
    __syncthreads();
    if (c < 3) {
        float v = sh[0][c] + sh[1][c] + sh[2][c] + sh[3][c];
        out[(size_t)n * 3 + c] = clip5(v);
    }
}

// ---------------- launch ----------------
extern "C" void kernel_launch(void* const* d_in, const int* in_sizes, int n_in,
                              void* d_out, int out_size)
{
    const float* z      = (const float*)d_in[0];
    const float* pos    = (const float*)d_in[1];
    const int*   ei     = (const int*)  d_in[2];
    const float* in_w   = (const float*)d_in[3];
    const float* in_b   = (const float*)d_in[4];
    const float* filt_w = (const float*)d_in[5];
    const float* filt_b = (const float*)d_in[6];
    const float* iw1    = (const float*)d_in[7];
    const float* ib1    = (const float*)d_in[8];
    const float* iw2    = (const float*)d_in[9];
    const float* ib2    = (const float*)d_in[10];
    const float* mmw    = (const float*)d_in[11];
    const float* mw1    = (const float*)d_in[12];
    const float* mb1    = (const float*)d_in[13];
    const float* mw2    = (const float*)d_in[14];
    const float* mb2    = (const float*)d_in[15];
    const float* mpw    = (const float*)d_in[16];
    const float* lng    = (const float*)d_in[17];
    const float* lnb    = (const float*)d_in[18];
    float* out = (float*)d_out;

    float *p_q, *p_x, *p_h, *p_mu, *p_mu2, *p_mumix, *p_ctx, *p_xm;
    cudaGetSymbolAddress((void**)&p_q,     g_q);
    cudaGetSymbolAddress((void**)&p_h,     g_h);
    cudaGetSymbolAddress((void**)&p_x,     g_x);
    cudaGetSymbolAddress((void**)&p_mu,    g_mu);
    cudaGetSymbolAddress((void**)&p_mu2,   g_mu2);
    cudaGetSymbolAddress((void**)&p_mumix, g_mumix);
    cudaGetSymbolAddress((void**)&p_ctx,   g_ctx);
    cudaGetSymbolAddress((void**)&p_xm,    g_xm);

    int gy_n  = (NN + 127) / 128;        // 157
    int gy_3n = (3 * NN + 127) / 128;    // 469

    init_bufs<<<(NN * DD3 + 255) / 256, 256>>>();
    csr_count<<<(NE + 255) / 256, 256>>>(ei);
    csr_scan<<<1, 1024>>>();
    csr_fill<<<(NE + 255) / 256, 256>>>(ei);

    tgemm<1><<<dim3(1, gy_n), 256>>>(z, in_w, in_b, p_q, NN, 64, DD);
    edge_pre<<<(NE + 7) / 8, 256>>>(pos, ei, filt_w, filt_b);

    float* mu_in = p_mu;
    float* mu_out = p_mu2;
    for (int l = 0; l < LNUM; l++) {
        tgemm<1><<<dim3(1, gy_n), 256>>>(p_q, iw1 + (size_t)l * DD * DD, ib1 + (size_t)l * DD,
                                         p_h, NN, DD, DD);
        tgemm<0><<<dim3(3, gy_n), 256>>>(p_h, iw2 + (size_t)l * DD * DD3, ib2 + (size_t)l * DD3,
                                         p_x, NN, DD, DD3);
        gather_msg<<<NN, 128>>>(mu_in, mu_out);
        tgemm<0><<<dim3(2, gy_3n), 256>>>(mu_out, mmw + (size_t)l * DD * 256, nullptr,
                                          p_mumix, 3 * NN, DD, 256);
        reduce_mix<<<NN, 128>>>();
        tgemm<1><<<dim3(1, gy_n), 256>>>(p_ctx, mw1 + (size_t)l * 256 * DD, mb1 + (size_t)l * DD,
                                         p_h, NN, 256, DD);
        tgemm<0><<<dim3(3, gy_n), 256>>>(p_h, mw2 + (size_t)l * DD * DD3, mb2 + (size_t)l * DD3,
                                         p_xm, NN, DD, DD3);
        update_node<<<NN, 128>>>(mu_out);
        float* tmp = mu_in; mu_in = mu_out; mu_out = tmp;
    }

    layernorm_out<<<NN, 128>>>(lng, lnb, out);
    pos_gather<<<NN, 128>>>(mu_in, mpw, out + (size_t)NN * DD);
}